// round 1
// baseline (speedup 1.0000x reference)
#include <cuda_runtime.h>
#include <cstdint>
#include <cstddef>

#define BB 64
#define SS 197
#define DD 768
#define PP 196
#define NROWS (BB * PP)   // 12544

// Scratch: blended A matrix and per-row weight sums (device globals; no allocs).
__device__ float g_Xs[(size_t)NROWS * DD];
__device__ float g_wsum[NROWS];

// ---------------------------------------------------------------------------
// Kernel 1: per (b,p) compute bilinear indices/weights, blend 4 rows of x.
// One block per output row, 192 threads * float4 = 768 floats.
// ---------------------------------------------------------------------------
__global__ __launch_bounds__(192) void blend_kernel(
    const float* __restrict__ x,
    const int*   __restrict__ img_ids,
    const float* __restrict__ avgs,
    const float* __restrict__ stds,
    const float* __restrict__ noise)
{
    const int r = blockIdx.x;          // 0..NROWS-1
    const int b = r / PP;
    const int p = r - b * PP;

    __shared__ int   si[4];
    __shared__ float sw[4];
    __shared__ float swsum;

    if (threadIdx.x == 0) {
        const int id = img_ids[b];
        const size_t abase = (size_t)id * (2 * PP);
        const float ax = avgs[abase + p];
        const float ay = avgs[abase + PP + p];
        const float sx = stds[abase + p];
        const float sy = stds[abase + PP + p];
        const float nx = noise[(size_t)b * 2 * PP + p];
        const float ny = noise[(size_t)b * 2 * PP + PP + p];
        const float kx = (nx - ax) / sx;
        const float ky = (ny - ay) / sy;
        const float x1 = ceilf(kx),  x2 = floorf(kx);
        const float y1 = ceilf(ky),  y2 = floorf(ky);
        const float wx1 = 1.0f - fabsf(x1 - kx);
        const float wx2 = 1.0f - fabsf(x2 - kx);
        const float wy1 = 1.0f - fabsf(y1 - ky);
        const float wy2 = 1.0f - fabsf(y2 - ky);
        const float w[4]  = {wx1 * wy1, wx2 * wy1, wx1 * wy2, wx2 * wy2};
        const float pxv[4] = {x1, x2, x1, x2};
        const float pyv[4] = {y1, y1, y2, y2};
        float tsum = 0.0f;
        #pragma unroll
        for (int j = 0; j < 4; ++j) {
            int t = (int)(14.0f * pyv[j] + pxv[j]);  // trunc toward zero (matches astype)
            t %= SS;
            if (t < 0) t += SS;                       // numpy mod: sign of divisor
            si[j] = t;
            sw[j] = w[j];
            tsum += w[j];
        }
        swsum = tsum;
    }
    __syncthreads();

    const int d4 = threadIdx.x;  // float4 index 0..191
    const float4* xb = (const float4*)(x + (size_t)b * SS * DD);
    const float w0 = sw[0], w1 = sw[1], w2 = sw[2], w3 = sw[3];
    const float4 v0 = xb[(size_t)si[0] * (DD / 4) + d4];
    const float4 v1 = xb[(size_t)si[1] * (DD / 4) + d4];
    const float4 v2 = xb[(size_t)si[2] * (DD / 4) + d4];
    const float4 v3 = xb[(size_t)si[3] * (DD / 4) + d4];
    float4 o;
    o.x = w0 * v0.x + w1 * v1.x + w2 * v2.x + w3 * v3.x;
    o.y = w0 * v0.y + w1 * v1.y + w2 * v2.y + w3 * v3.y;
    o.z = w0 * v0.z + w1 * v1.z + w2 * v2.z + w3 * v3.z;
    o.w = w0 * v0.w + w1 * v1.w + w2 * v2.w + w3 * v3.w;
    ((float4*)(g_Xs + (size_t)r * DD))[d4] = o;
    if (threadIdx.x == 0) g_wsum[r] = swsum;
}

// ---------------------------------------------------------------------------
// Kernel 2: class-token rows -> 1.0 (attn==1, class_emb==ones)
// ---------------------------------------------------------------------------
__global__ __launch_bounds__(192) void cls_kernel(float* __restrict__ out)
{
    const float4 one = make_float4(1.0f, 1.0f, 1.0f, 1.0f);
    ((float4*)(out + (size_t)blockIdx.x * SS * DD))[threadIdx.x] = one;
}

// ---------------------------------------------------------------------------
// Kernel 3: C[12544,768] = g_Xs @ Wv, epilogue adds wsum[m]*bv[n] and
// scatters row m into out[b*S + 1 + (m % P)].
// 128x128x8 tiles, 256 threads, 8x8 per thread (split 4+4 for bank-free LDS).
// ---------------------------------------------------------------------------
__global__ __launch_bounds__(256, 2) void gemm_kernel(
    const float* __restrict__ Wv,
    const float* __restrict__ bv,
    float* __restrict__ out)
{
    __shared__ float As[2][8][128];
    __shared__ float Bs[2][8][128];

    const int bn = blockIdx.x * 128;
    const int bm = blockIdx.y * 128;
    const int tid = threadIdx.x;

    const int arow = tid >> 1;
    const int acol = (tid & 1) << 2;
    const int brow = tid >> 5;
    const int bcol = (tid & 31) << 2;

    const float* Ap = g_Xs + (size_t)(bm + arow) * DD + acol;
    const float* Bp = Wv + (size_t)brow * DD + bn + bcol;

    const int tx = tid & 15;
    const int ty = tid >> 4;

    float acc[8][8];
    #pragma unroll
    for (int i = 0; i < 8; ++i)
        #pragma unroll
        for (int j = 0; j < 8; ++j) acc[i][j] = 0.0f;

    // prologue: stage 0
    float4 a  = *(const float4*)Ap;
    float4 bb = *(const float4*)Bp;
    As[0][acol + 0][arow] = a.x;
    As[0][acol + 1][arow] = a.y;
    As[0][acol + 2][arow] = a.z;
    As[0][acol + 3][arow] = a.w;
    *(float4*)&Bs[0][brow][bcol] = bb;
    __syncthreads();

    const int KT = DD / 8;  // 96
    #pragma unroll 1
    for (int kt = 0; kt < KT; ++kt) {
        const int cur = kt & 1;
        if (kt < KT - 1) {
            a  = *(const float4*)(Ap + (kt + 1) * 8);
            bb = *(const float4*)(Bp + (size_t)(kt + 1) * 8 * DD);
        }
        #pragma unroll
        for (int k = 0; k < 8; ++k) {
            float ar[8], br[8];
            *(float4*)&ar[0] = *(const float4*)&As[cur][k][ty * 4];
            *(float4*)&ar[4] = *(const float4*)&As[cur][k][64 + ty * 4];
            *(float4*)&br[0] = *(const float4*)&Bs[cur][k][tx * 4];
            *(float4*)&br[4] = *(const float4*)&Bs[cur][k][64 + tx * 4];
            #pragma unroll
            for (int i = 0; i < 8; ++i)
                #pragma unroll
                for (int j = 0; j < 8; ++j)
                    acc[i][j] += ar[i] * br[j];
        }
        if (kt < KT - 1) {
            const int nxt = cur ^ 1;
            As[nxt][acol + 0][arow] = a.x;
            As[nxt][acol + 1][arow] = a.y;
            As[nxt][acol + 2][arow] = a.z;
            As[nxt][acol + 3][arow] = a.w;
            *(float4*)&Bs[nxt][brow][bcol] = bb;
            __syncthreads();
        }
    }

    // epilogue: + wsum[m]*bv[n], scatter to out rows
    float bvv[8];
    *(float4*)&bvv[0] = *(const float4*)(bv + bn + tx * 4);
    *(float4*)&bvv[4] = *(const float4*)(bv + bn + 64 + tx * 4);

    #pragma unroll
    for (int i = 0; i < 8; ++i) {
        const int mrow = (i < 4) ? (ty * 4 + i) : (64 + ty * 4 + (i - 4));
        const int m = bm + mrow;
        const int b_ = m / PP;
        const int srow = 1 + (m - b_ * PP);
        const float ws = g_wsum[m];
        float* op = out + ((size_t)b_ * SS + srow) * DD + bn;
        float4 o1, o2;
        o1.x = acc[i][0] + ws * bvv[0];
        o1.y = acc[i][1] + ws * bvv[1];
        o1.z = acc[i][2] + ws * bvv[2];
        o1.w = acc[i][3] + ws * bvv[3];
        o2.x = acc[i][4] + ws * bvv[4];
        o2.y = acc[i][5] + ws * bvv[5];
        o2.z = acc[i][6] + ws * bvv[6];
        o2.w = acc[i][7] + ws * bvv[7];
        *(float4*)(op + tx * 4)      = o1;
        *(float4*)(op + 64 + tx * 4) = o2;
    }
}

// ---------------------------------------------------------------------------
// Launch. Inputs (metadata order): x, img_ids, mask, Wq, bq, Wk, bk, Wv, bv,
// avgs, std_devs, noise. q/k path is dead code (softmax over singleton == 1).
// ---------------------------------------------------------------------------
extern "C" void kernel_launch(void* const* d_in, const int* in_sizes, int n_in,
                              void* d_out, int out_size)
{
    const float* x       = (const float*)d_in[0];
    const int*   img_ids = (const int*)  d_in[1];
    const float* Wv      = (const float*)d_in[7];
    const float* bv      = (const float*)d_in[8];
    const float* avgs    = (const float*)d_in[9];
    const float* stds    = (const float*)d_in[10];
    const float* noise   = (const float*)d_in[11];
    float* out = (float*)d_out;

    blend_kernel<<<NROWS, 192>>>(x, img_ids, avgs, stds, noise);
    cls_kernel<<<BB, 192>>>(out);
    gemm_kernel<<<dim3(DD / 128, NROWS / 128), 256>>>(Wv, bv, out);
}

// round 3
// speedup vs baseline: 1.5965x; 1.5965x over previous
#include <cuda_runtime.h>
#include <cuda_bf16.h>
#include <cstdint>
#include <cstddef>

#define BB 64
#define SS 197
#define DD 768
#define PP 196
#define NROWS (BB * PP)   // 12544

// ---------------------------------------------------------------------------
// Device scratch (no allocs allowed)
// ---------------------------------------------------------------------------
__device__ __nv_bfloat16 g_Ahi[(size_t)NROWS * DD];
__device__ __nv_bfloat16 g_Alo[(size_t)NROWS * DD];
__device__ __nv_bfloat16 g_Bhi[(size_t)DD * DD];   // [n][k] = Wv[k][n] hi
__device__ __nv_bfloat16 g_Blo[(size_t)DD * DD];   // lo residual
__device__ float g_wsum[NROWS];

// ---------------------------------------------------------------------------
// helpers
// ---------------------------------------------------------------------------
__device__ __forceinline__ uint32_t smem_u32(const void* p) {
    uint32_t a;
    asm("{ .reg .u64 t; cvta.to.shared.u64 t, %1; cvt.u32.u64 %0, t; }"
        : "=r"(a) : "l"(p));
    return a;
}

__device__ __forceinline__ void cp16(uint32_t dst, const void* src) {
    asm volatile("cp.async.cg.shared.global [%0], [%1], 16;\n"
                 :: "r"(dst), "l"(src));
}

__device__ __forceinline__ uint32_t lds32(uint32_t a) {
    uint32_t v;
    asm volatile("ld.shared.b32 %0, [%1];" : "=r"(v) : "r"(a));
    return v;
}

__device__ __forceinline__ void mma16816(float* c, const uint32_t* a,
                                         const uint32_t* b) {
    asm volatile(
        "mma.sync.aligned.m16n8k16.row.col.f32.bf16.bf16.f32 "
        "{%0,%1,%2,%3}, {%4,%5,%6,%7}, {%8,%9}, {%0,%1,%2,%3};"
        : "+f"(c[0]), "+f"(c[1]), "+f"(c[2]), "+f"(c[3])
        : "r"(a[0]), "r"(a[1]), "r"(a[2]), "r"(a[3]), "r"(b[0]), "r"(b[1]));
}

// ---------------------------------------------------------------------------
// Kernel 1: bilinear blend -> bf16 hi/lo split of A
// ---------------------------------------------------------------------------
__global__ __launch_bounds__(192) void blend_kernel(
    const float* __restrict__ x,
    const int*   __restrict__ img_ids,
    const float* __restrict__ avgs,
    const float* __restrict__ stds,
    const float* __restrict__ noise)
{
    const int r = blockIdx.x;
    const int b = r / PP;
    const int p = r - b * PP;

    __shared__ int   si[4];
    __shared__ float sw[4];
    __shared__ float swsum;

    if (threadIdx.x == 0) {
        const int id = img_ids[b];
        const size_t abase = (size_t)id * (2 * PP);
        const float ax = avgs[abase + p];
        const float ay = avgs[abase + PP + p];
        const float sx = stds[abase + p];
        const float sy = stds[abase + PP + p];
        const float nx = noise[(size_t)b * 2 * PP + p];
        const float ny = noise[(size_t)b * 2 * PP + PP + p];
        const float kx = (nx - ax) / sx;
        const float ky = (ny - ay) / sy;
        const float x1 = ceilf(kx),  x2 = floorf(kx);
        const float y1 = ceilf(ky),  y2 = floorf(ky);
        const float wx1 = 1.0f - fabsf(x1 - kx);
        const float wx2 = 1.0f - fabsf(x2 - kx);
        const float wy1 = 1.0f - fabsf(y1 - ky);
        const float wy2 = 1.0f - fabsf(y2 - ky);
        const float w[4]   = {wx1 * wy1, wx2 * wy1, wx1 * wy2, wx2 * wy2};
        const float pxv[4] = {x1, x2, x1, x2};
        const float pyv[4] = {y1, y1, y2, y2};
        float tsum = 0.0f;
        #pragma unroll
        for (int j = 0; j < 4; ++j) {
            int t = (int)(14.0f * pyv[j] + pxv[j]);
            t %= SS;
            if (t < 0) t += SS;
            si[j] = t;
            sw[j] = w[j];
            tsum += w[j];
        }
        swsum = tsum;
    }
    __syncthreads();

    const int d4 = threadIdx.x;
    const float4* xb = (const float4*)(x + (size_t)b * SS * DD);
    const float w0 = sw[0], w1 = sw[1], w2 = sw[2], w3 = sw[3];
    const float4 v0 = xb[(size_t)si[0] * (DD / 4) + d4];
    const float4 v1 = xb[(size_t)si[1] * (DD / 4) + d4];
    const float4 v2 = xb[(size_t)si[2] * (DD / 4) + d4];
    const float4 v3 = xb[(size_t)si[3] * (DD / 4) + d4];
    float o[4];
    o[0] = w0 * v0.x + w1 * v1.x + w2 * v2.x + w3 * v3.x;
    o[1] = w0 * v0.y + w1 * v1.y + w2 * v2.y + w3 * v3.y;
    o[2] = w0 * v0.z + w1 * v1.z + w2 * v2.z + w3 * v3.z;
    o[3] = w0 * v0.w + w1 * v1.w + w2 * v2.w + w3 * v3.w;

    ushort4 hv, lv;
    unsigned short* hp = (unsigned short*)&hv;
    unsigned short* lp = (unsigned short*)&lv;
    #pragma unroll
    for (int j = 0; j < 4; ++j) {
        __nv_bfloat16 h = __float2bfloat16_rn(o[j]);
        float res = o[j] - __bfloat162float(h);
        __nv_bfloat16 l = __float2bfloat16_rn(res);
        hp[j] = __bfloat16_as_ushort(h);
        lp[j] = __bfloat16_as_ushort(l);
    }
    ((ushort4*)g_Ahi)[(size_t)r * (DD / 4) + d4] = hv;
    ((ushort4*)g_Alo)[(size_t)r * (DD / 4) + d4] = lv;
    if (threadIdx.x == 0) g_wsum[r] = swsum;
}

// ---------------------------------------------------------------------------
// Kernel 2: transpose + bf16 split of Wv -> B[n][k]
// ---------------------------------------------------------------------------
__global__ __launch_bounds__(256) void wsplit_kernel(const float* __restrict__ W)
{
    __shared__ float t[32][33];
    const int n0 = blockIdx.x * 32, k0 = blockIdx.y * 32;
    const int tx = threadIdx.x & 31, ty = threadIdx.x >> 5;
    #pragma unroll
    for (int r = ty; r < 32; r += 8)
        t[r][tx] = W[(size_t)(k0 + r) * DD + n0 + tx];
    __syncthreads();
    #pragma unroll
    for (int r = ty; r < 32; r += 8) {
        float v = t[tx][r];   // = W[k0+tx][n0+r]
        __nv_bfloat16 h = __float2bfloat16_rn(v);
        float res = v - __bfloat162float(h);
        size_t off = (size_t)(n0 + r) * DD + k0 + tx;
        g_Bhi[off] = h;
        g_Blo[off] = __float2bfloat16_rn(res);
    }
}

// ---------------------------------------------------------------------------
// Kernel 3: class-token rows -> 1.0
// ---------------------------------------------------------------------------
__global__ __launch_bounds__(192) void cls_kernel(float* __restrict__ out)
{
    const float4 one = make_float4(1.0f, 1.0f, 1.0f, 1.0f);
    ((float4*)(out + (size_t)blockIdx.x * SS * DD))[threadIdx.x] = one;
}

// ---------------------------------------------------------------------------
// Kernel 4: mma.sync bf16-split GEMM.
// CTA 128x128, 8 warps (warp tile 64x32), Kstage=32, 4-stage cp.async.
// smem pitch 40 bf16 (80B) -> conflict-free b32 fragment loads.
// 3 passes per k16 (hh, lh, hl) into one fp32 accumulator.
// ---------------------------------------------------------------------------
#define PCH_B 80               // row pitch bytes (40 bf16)
#define ARR_B (128 * PCH_B)    // 10240 bytes per array
#define STG_B (4 * ARR_B)      // 40960 bytes per stage
#define OFF_AH 0
#define OFF_AL ARR_B
#define OFF_BH (2 * ARR_B)
#define OFF_BL (3 * ARR_B)
#define NSTAGE 4
#define KSTEPS 24              // 768 / 32
#define GEMM_SMEM (NSTAGE * STG_B)   // 163840

__device__ __forceinline__ void load_stage(uint32_t sbase, int k0,
                                           int bm, int bn, int tid)
{
    const int row = tid >> 1;          // 0..127
    const int ch  = (tid & 1) * 2;     // chunk 0 or 2 (16B chunks)
    const uint32_t doff = (uint32_t)row * PCH_B + (uint32_t)ch * 16;
    const int kk = k0 + ch * 8;        // element offset in k

    const __nv_bfloat16* pAh = g_Ahi + (size_t)(bm + row) * DD + kk;
    const __nv_bfloat16* pAl = g_Alo + (size_t)(bm + row) * DD + kk;
    const __nv_bfloat16* pBh = g_Bhi + (size_t)(bn + row) * DD + kk;
    const __nv_bfloat16* pBl = g_Blo + (size_t)(bn + row) * DD + kk;

    cp16(sbase + OFF_AH + doff,      pAh);
    cp16(sbase + OFF_AH + doff + 16, pAh + 8);
    cp16(sbase + OFF_AL + doff,      pAl);
    cp16(sbase + OFF_AL + doff + 16, pAl + 8);
    cp16(sbase + OFF_BH + doff,      pBh);
    cp16(sbase + OFF_BH + doff + 16, pBh + 8);
    cp16(sbase + OFF_BL + doff,      pBl);
    cp16(sbase + OFF_BL + doff + 16, pBl + 8);
}

__global__ __launch_bounds__(256, 1) void gemm_kernel(
    const float* __restrict__ bv,
    float* __restrict__ out)
{
    extern __shared__ char smem[];
    const uint32_t sb = smem_u32(smem);
    const int tid = threadIdx.x;
    const int lid = tid & 31;
    const int wid = tid >> 5;
    const int bm = blockIdx.y * 128;
    const int bn = blockIdx.x * 128;
    const int wm = (wid & 1) * 64;
    const int wn = (wid >> 1) * 32;

    float acc[4][4][4];
    #pragma unroll
    for (int i = 0; i < 4; ++i)
        #pragma unroll
        for (int j = 0; j < 4; ++j)
            #pragma unroll
            for (int q = 0; q < 4; ++q) acc[i][j][q] = 0.0f;

    // prologue: stages 0..2
    load_stage(sb + 0 * STG_B, 0,  bm, bn, tid);
    asm volatile("cp.async.commit_group;" ::: "memory");
    load_stage(sb + 1 * STG_B, 32, bm, bn, tid);
    asm volatile("cp.async.commit_group;" ::: "memory");
    load_stage(sb + 2 * STG_B, 64, bm, bn, tid);
    asm volatile("cp.async.commit_group;" ::: "memory");

    const int lr  = lid >> 2;
    const uint32_t lc4 = (lid & 3) * 4;
    const uint32_t aoff = (uint32_t)(wm + lr) * PCH_B + lc4;
    const uint32_t boff = (uint32_t)(wn + lr) * PCH_B + lc4;

    #pragma unroll 1
    for (int s = 0; s < KSTEPS; ++s) {
        asm volatile("cp.async.wait_group 2;" ::: "memory");
        __syncthreads();

        if (s + 3 < KSTEPS)
            load_stage(sb + ((s + 3) & 3) * STG_B, (s + 3) * 32, bm, bn, tid);
        asm volatile("cp.async.commit_group;" ::: "memory");

        const uint32_t st = sb + (s & 3) * STG_B;
        #pragma unroll
        for (int kb2 = 0; kb2 < 2; ++kb2) {
            const uint32_t kb = kb2 * 32;   // 16 bf16 = 32 bytes
            uint32_t Ah[4][4], Al[4][4], Bh[4][2], Bl[4][2];
            #pragma unroll
            for (int mt = 0; mt < 4; ++mt) {
                uint32_t base = st + OFF_AH + aoff + mt * (16 * PCH_B) + kb;
                Ah[mt][0] = lds32(base);
                Ah[mt][1] = lds32(base + 8 * PCH_B);
                Ah[mt][2] = lds32(base + 16);
                Ah[mt][3] = lds32(base + 8 * PCH_B + 16);
                base += ARR_B;
                Al[mt][0] = lds32(base);
                Al[mt][1] = lds32(base + 8 * PCH_B);
                Al[mt][2] = lds32(base + 16);
                Al[mt][3] = lds32(base + 8 * PCH_B + 16);
            }
            #pragma unroll
            for (int nt = 0; nt < 4; ++nt) {
                uint32_t base = st + OFF_BH + boff + nt * (8 * PCH_B) + kb;
                Bh[nt][0] = lds32(base);
                Bh[nt][1] = lds32(base + 16);
                base += ARR_B;
                Bl[nt][0] = lds32(base);
                Bl[nt][1] = lds32(base + 16);
            }
            #pragma unroll
            for (int mt = 0; mt < 4; ++mt)
                #pragma unroll
                for (int nt = 0; nt < 4; ++nt)
                    mma16816(acc[mt][nt], Ah[mt], Bh[nt]);
            #pragma unroll
            for (int mt = 0; mt < 4; ++mt)
                #pragma unroll
                for (int nt = 0; nt < 4; ++nt)
                    mma16816(acc[mt][nt], Al[mt], Bh[nt]);
            #pragma unroll
            for (int mt = 0; mt < 4; ++mt)
                #pragma unroll
                for (int nt = 0; nt < 4; ++nt)
                    mma16816(acc[mt][nt], Ah[mt], Bl[nt]);
        }
    }

    // epilogue: D + wsum[m]*bv[n], scatter row m -> out[b, 1+p, :]
    const int lr2 = lid >> 2;
    const int lc  = (lid & 3) * 2;
    #pragma unroll
    for (int mt = 0; mt < 4; ++mt) {
        #pragma unroll
        for (int half = 0; half < 2; ++half) {
            const int m = bm + wm + mt * 16 + lr2 + half * 8;
            const float ws = g_wsum[m];
            const int b_ = m / PP;
            const int srow = 1 + (m - b_ * PP);
            float* op = out + ((size_t)b_ * SS + srow) * DD + bn + wn;
            #pragma unroll
            for (int nt = 0; nt < 4; ++nt) {
                const float2 bb = *(const float2*)(bv + bn + wn + nt * 8 + lc);
                float2 o;
                o.x = acc[mt][nt][half * 2 + 0] + ws * bb.x;
                o.y = acc[mt][nt][half * 2 + 1] + ws * bb.y;
                *(float2*)(op + nt * 8 + lc) = o;
            }
        }
    }
}

// ---------------------------------------------------------------------------
// Launch
// ---------------------------------------------------------------------------
extern "C" void kernel_launch(void* const* d_in, const int* in_sizes, int n_in,
                              void* d_out, int out_size)
{
    const float* x       = (const float*)d_in[0];
    const int*   img_ids = (const int*)  d_in[1];
    const float* Wv      = (const float*)d_in[7];
    const float* bv      = (const float*)d_in[8];
    const float* avgs    = (const float*)d_in[9];
    const float* stds    = (const float*)d_in[10];
    const float* noise   = (const float*)d_in[11];
    float* out = (float*)d_out;

    cudaFuncSetAttribute(gemm_kernel,
                         cudaFuncAttributeMaxDynamicSharedMemorySize, GEMM_SMEM);

    blend_kernel<<<NROWS, 192>>>(x, img_ids, avgs, stds, noise);
    wsplit_kernel<<<dim3(24, 24), 256>>>(Wv);
    cls_kernel<<<BB, 192>>>(out);
    gemm_kernel<<<dim3(DD / 128, NROWS / 128), 256, GEMM_SMEM>>>(bv, out);
}

// round 4
// speedup vs baseline: 2.4435x; 1.5305x over previous
#include <cuda_runtime.h>
#include <cuda_bf16.h>
#include <cuda_fp16.h>
#include <cstdint>
#include <cstddef>

#define BB 64
#define SS 197
#define DD 768
#define PP 196
#define NROWS (BB * PP)   // 12544

// ---------------------------------------------------------------------------
// Device scratch (no allocs allowed)
// ---------------------------------------------------------------------------
__device__ __half g_Ahi[(size_t)NROWS * DD];
__device__ __half g_Alo[(size_t)NROWS * DD];
__device__ __half g_Bh[(size_t)DD * DD];   // [n][k] = Wv[k][n] fp16
__device__ float g_wsum[NROWS];

// ---------------------------------------------------------------------------
// helpers
// ---------------------------------------------------------------------------
__device__ __forceinline__ uint32_t smem_u32(const void* p) {
    uint32_t a;
    asm("{ .reg .u64 t; cvta.to.shared.u64 t, %1; cvt.u32.u64 %0, t; }"
        : "=r"(a) : "l"(p));
    return a;
}

__device__ __forceinline__ void cp16(uint32_t dst, const void* src) {
    asm volatile("cp.async.cg.shared.global [%0], [%1], 16;\n"
                 :: "r"(dst), "l"(src));
}

__device__ __forceinline__ uint32_t lds32(uint32_t a) {
    uint32_t v;
    asm volatile("ld.shared.b32 %0, [%1];" : "=r"(v) : "r"(a));
    return v;
}

__device__ __forceinline__ void ldsm_x4(uint32_t* r, uint32_t a) {
    asm volatile("ldmatrix.sync.aligned.m8n8.x4.shared.b16 {%0,%1,%2,%3}, [%4];"
                 : "=r"(r[0]), "=r"(r[1]), "=r"(r[2]), "=r"(r[3]) : "r"(a));
}

__device__ __forceinline__ void mma16816(float* c, const uint32_t* a,
                                         const uint32_t* b) {
    asm volatile(
        "mma.sync.aligned.m16n8k16.row.col.f32.f16.f16.f32 "
        "{%0,%1,%2,%3}, {%4,%5,%6,%7}, {%8,%9}, {%0,%1,%2,%3};"
        : "+f"(c[0]), "+f"(c[1]), "+f"(c[2]), "+f"(c[3])
        : "r"(a[0]), "r"(a[1]), "r"(a[2]), "r"(a[3]), "r"(b[0]), "r"(b[1]));
}

// ---------------------------------------------------------------------------
// Kernel 1: bilinear blend -> fp16 hi/lo split of A
// ---------------------------------------------------------------------------
__global__ __launch_bounds__(192) void blend_kernel(
    const float* __restrict__ x,
    const int*   __restrict__ img_ids,
    const float* __restrict__ avgs,
    const float* __restrict__ stds,
    const float* __restrict__ noise)
{
    const int r = blockIdx.x;
    const int b = r / PP;
    const int p = r - b * PP;

    __shared__ int   si[4];
    __shared__ float sw[4];
    __shared__ float swsum;

    if (threadIdx.x == 0) {
        const int id = img_ids[b];
        const size_t abase = (size_t)id * (2 * PP);
        const float ax = avgs[abase + p];
        const float ay = avgs[abase + PP + p];
        const float sx = stds[abase + p];
        const float sy = stds[abase + PP + p];
        const float nx = noise[(size_t)b * 2 * PP + p];
        const float ny = noise[(size_t)b * 2 * PP + PP + p];
        const float kx = (nx - ax) / sx;
        const float ky = (ny - ay) / sy;
        const float x1 = ceilf(kx),  x2 = floorf(kx);
        const float y1 = ceilf(ky),  y2 = floorf(ky);
        const float wx1 = 1.0f - fabsf(x1 - kx);
        const float wx2 = 1.0f - fabsf(x2 - kx);
        const float wy1 = 1.0f - fabsf(y1 - ky);
        const float wy2 = 1.0f - fabsf(y2 - ky);
        const float w[4]   = {wx1 * wy1, wx2 * wy1, wx1 * wy2, wx2 * wy2};
        const float pxv[4] = {x1, x2, x1, x2};
        const float pyv[4] = {y1, y1, y2, y2};
        float tsum = 0.0f;
        #pragma unroll
        for (int j = 0; j < 4; ++j) {
            int t = (int)(14.0f * pyv[j] + pxv[j]);
            t %= SS;
            if (t < 0) t += SS;
            si[j] = t;
            sw[j] = w[j];
            tsum += w[j];
        }
        swsum = tsum;
    }
    __syncthreads();

    const int d4 = threadIdx.x;
    const float4* xb = (const float4*)(x + (size_t)b * SS * DD);
    const float w0 = sw[0], w1 = sw[1], w2 = sw[2], w3 = sw[3];
    const float4 v0 = xb[(size_t)si[0] * (DD / 4) + d4];
    const float4 v1 = xb[(size_t)si[1] * (DD / 4) + d4];
    const float4 v2 = xb[(size_t)si[2] * (DD / 4) + d4];
    const float4 v3 = xb[(size_t)si[3] * (DD / 4) + d4];
    float o[4];
    o[0] = w0 * v0.x + w1 * v1.x + w2 * v2.x + w3 * v3.x;
    o[1] = w0 * v0.y + w1 * v1.y + w2 * v2.y + w3 * v3.y;
    o[2] = w0 * v0.z + w1 * v1.z + w2 * v2.z + w3 * v3.z;
    o[3] = w0 * v0.w + w1 * v1.w + w2 * v2.w + w3 * v3.w;

    ushort4 hv, lv;
    unsigned short* hp = (unsigned short*)&hv;
    unsigned short* lp = (unsigned short*)&lv;
    #pragma unroll
    for (int j = 0; j < 4; ++j) {
        __half h = __float2half_rn(o[j]);
        float res = o[j] - __half2float(h);
        __half l = __float2half_rn(res);
        hp[j] = __half_as_ushort(h);
        lp[j] = __half_as_ushort(l);
    }
    ((ushort4*)g_Ahi)[(size_t)r * (DD / 4) + d4] = hv;
    ((ushort4*)g_Alo)[(size_t)r * (DD / 4) + d4] = lv;
    if (threadIdx.x == 0) g_wsum[r] = swsum;
}

// ---------------------------------------------------------------------------
// Kernel 2: transpose Wv -> fp16 B[n][k]
// ---------------------------------------------------------------------------
__global__ __launch_bounds__(256) void wsplit_kernel(const float* __restrict__ W)
{
    __shared__ float t[32][33];
    const int n0 = blockIdx.x * 32, k0 = blockIdx.y * 32;
    const int tx = threadIdx.x & 31, ty = threadIdx.x >> 5;
    #pragma unroll
    for (int r = ty; r < 32; r += 8)
        t[r][tx] = W[(size_t)(k0 + r) * DD + n0 + tx];
    __syncthreads();
    #pragma unroll
    for (int r = ty; r < 32; r += 8)
        g_Bh[(size_t)(n0 + r) * DD + k0 + tx] = __float2half_rn(t[tx][r]);
}

// ---------------------------------------------------------------------------
// Kernel 3: class-token rows -> 1.0
// ---------------------------------------------------------------------------
__global__ __launch_bounds__(192) void cls_kernel(float* __restrict__ out)
{
    const float4 one = make_float4(1.0f, 1.0f, 1.0f, 1.0f);
    ((float4*)(out + (size_t)blockIdx.x * SS * DD))[threadIdx.x] = one;
}

// ---------------------------------------------------------------------------
// Kernel 4: mma.sync fp16-split GEMM (2 passes: Ah*B + Al*B).
// CTA 128x128, 8 warps (warp 64x32), Kstage=32, 4-stage cp.async, 96KB smem
// -> 2 CTAs/SM. 64B-pitch rows, XOR chunk swizzle (c ^= (row>>1)&3) keeps
// ldmatrix + b32 fragment loads conflict-free. A frags via ldmatrix.x4.
// ---------------------------------------------------------------------------
#define ARR_B 8192               // 128 rows * 64B
#define STG_B (3 * ARR_B)        // 24576
#define OFF_AH 0
#define OFF_AL ARR_B
#define OFF_BH (2 * ARR_B)
#define NSTAGE 4
#define KSTEPS 24                // 768 / 32
#define GEMM_SMEM (NSTAGE * STG_B)   // 98304

__device__ __forceinline__ void load_stage(uint32_t sbase, int k0,
                                           int bm, int bn, int tid)
{
    const int row = tid >> 1;          // 0..127
    const int ch0 = (tid & 1) * 2;     // chunks {0,1} or {2,3}
    const int swz = (row >> 1) & 3;

    const __half* pAh = g_Ahi + (size_t)(bm + row) * DD + k0;
    const __half* pAl = g_Alo + (size_t)(bm + row) * DD + k0;
    const __half* pBh = g_Bh  + (size_t)(bn + row) * DD + k0;
    const uint32_t drow = sbase + (uint32_t)row * 64;

    #pragma unroll
    for (int j = 0; j < 2; ++j) {
        const int ch = ch0 + j;
        const uint32_t d = drow + ((ch ^ swz) << 4);
        const int kk = ch * 8;
        cp16(d + OFF_AH, pAh + kk);
        cp16(d + OFF_AL, pAl + kk);
        cp16(d + OFF_BH, pBh + kk);
    }
}

__global__ __launch_bounds__(256, 2) void gemm_kernel(
    const float* __restrict__ bv,
    float* __restrict__ out)
{
    extern __shared__ char smem[];
    const uint32_t sb = smem_u32(smem);
    const int tid = threadIdx.x;
    const int lid = tid & 31;
    const int wid = tid >> 5;
    const int bm = blockIdx.y * 128;
    const int bn = blockIdx.x * 128;
    const int wm = (wid & 1) * 64;
    const int wn = (wid >> 1) * 32;

    float acc[4][4][4];
    #pragma unroll
    for (int i = 0; i < 4; ++i)
        #pragma unroll
        for (int j = 0; j < 4; ++j)
            #pragma unroll
            for (int q = 0; q < 4; ++q) acc[i][j][q] = 0.0f;

    load_stage(sb + 0 * STG_B, 0,  bm, bn, tid);
    asm volatile("cp.async.commit_group;" ::: "memory");
    load_stage(sb + 1 * STG_B, 32, bm, bn, tid);
    asm volatile("cp.async.commit_group;" ::: "memory");
    load_stage(sb + 2 * STG_B, 64, bm, bn, tid);
    asm volatile("cp.async.commit_group;" ::: "memory");

    // A ldmatrix addressing: row = wm + (lid&15) (+ mt*16), chunk = kb2*2 + (lid>>4)
    const uint32_t a_row  = (uint32_t)(wm + (lid & 15));
    const uint32_t a_swz  = ((lid & 15) >> 1) & 3;
    const uint32_t a_chb  = (uint32_t)(lid >> 4);     // 0 or 1
    const uint32_t a_base = a_row * 64;
    // B b32 addressing: row n = wn + nt*8 + (lid>>2), word (lid&3)
    const uint32_t b_row  = (uint32_t)(wn + (lid >> 2));
    const uint32_t b_swz  = (lid >> 3) & 3;
    const uint32_t b_base = b_row * 64 + (uint32_t)(lid & 3) * 4;

    #pragma unroll 1
    for (int s = 0; s < KSTEPS; ++s) {
        asm volatile("cp.async.wait_group 2;" ::: "memory");
        __syncthreads();

        if (s + 3 < KSTEPS)
            load_stage(sb + ((s + 3) & 3) * STG_B, (s + 3) * 32, bm, bn, tid);
        asm volatile("cp.async.commit_group;" ::: "memory");

        const uint32_t st = sb + (s & 3) * STG_B;
        #pragma unroll
        for (int kb2 = 0; kb2 < 2; ++kb2) {
            uint32_t Ah[4][4], Al[4][4], Bh[4][2];
            const uint32_t a_ch = ((kb2 * 2 + a_chb) ^ a_swz) << 4;
            #pragma unroll
            for (int mt = 0; mt < 4; ++mt) {
                const uint32_t ad = st + a_base + mt * 1024 + a_ch;
                ldsm_x4(Ah[mt], ad + OFF_AH);
                ldsm_x4(Al[mt], ad + OFF_AL);
            }
            #pragma unroll
            for (int nt = 0; nt < 4; ++nt) {
                const uint32_t bd = st + OFF_BH + b_base + nt * 512;
                Bh[nt][0] = lds32(bd + (((kb2 * 2 + 0) ^ b_swz) << 4));
                Bh[nt][1] = lds32(bd + (((kb2 * 2 + 1) ^ b_swz) << 4));
            }
            #pragma unroll
            for (int mt = 0; mt < 4; ++mt)
                #pragma unroll
                for (int nt = 0; nt < 4; ++nt)
                    mma16816(acc[mt][nt], Ah[mt], Bh[nt]);
            #pragma unroll
            for (int mt = 0; mt < 4; ++mt)
                #pragma unroll
                for (int nt = 0; nt < 4; ++nt)
                    mma16816(acc[mt][nt], Al[mt], Bh[nt]);
        }
    }

    // epilogue: D + wsum[m]*bv[n], scatter row m -> out[b, 1+p, :]
    const int lr2 = lid >> 2;
    const int lc  = (lid & 3) * 2;
    #pragma unroll
    for (int mt = 0; mt < 4; ++mt) {
        #pragma unroll
        for (int half = 0; half < 2; ++half) {
            const int m = bm + wm + mt * 16 + lr2 + half * 8;
            const float ws = g_wsum[m];
            const int b_ = m / PP;
            const int srow = 1 + (m - b_ * PP);
            float* op = out + ((size_t)b_ * SS + srow) * DD + bn + wn;
            #pragma unroll
            for (int nt = 0; nt < 4; ++nt) {
                const float2 bb = *(const float2*)(bv + bn + wn + nt * 8 + lc);
                float2 o;
                o.x = acc[mt][nt][half * 2 + 0] + ws * bb.x;
                o.y = acc[mt][nt][half * 2 + 1] + ws * bb.y;
                *(float2*)(op + nt * 8 + lc) = o;
            }
        }
    }
}

// ---------------------------------------------------------------------------
// Launch
// ---------------------------------------------------------------------------
extern "C" void kernel_launch(void* const* d_in, const int* in_sizes, int n_in,
                              void* d_out, int out_size)
{
    const float* x       = (const float*)d_in[0];
    const int*   img_ids = (const int*)  d_in[1];
    const float* Wv      = (const float*)d_in[7];
    const float* bv      = (const float*)d_in[8];
    const float* avgs    = (const float*)d_in[9];
    const float* stds    = (const float*)d_in[10];
    const float* noise   = (const float*)d_in[11];
    float* out = (float*)d_out;

    cudaFuncSetAttribute(gemm_kernel,
                         cudaFuncAttributeMaxDynamicSharedMemorySize, GEMM_SMEM);

    blend_kernel<<<NROWS, 192>>>(x, img_ids, avgs, stds, noise);
    wsplit_kernel<<<dim3(24, 24), 256>>>(Wv);
    cls_kernel<<<BB, 192>>>(out);
    gemm_kernel<<<dim3(DD / 128, NROWS / 128), 256, GEMM_SMEM>>>(bv, out);
}

// round 5
// speedup vs baseline: 3.5944x; 1.4710x over previous
#include <cuda_runtime.h>
#include <cuda_bf16.h>
#include <cuda_fp16.h>
#include <cstdint>
#include <cstddef>

#define BB 64
#define SS 197
#define DD 768
#define PP 196
#define NROWS (BB * PP)   // 12544

// ---------------------------------------------------------------------------
// Device scratch (no allocs allowed)
// ---------------------------------------------------------------------------
__device__ __half g_Ah[(size_t)NROWS * DD];
__device__ __half g_Bh[(size_t)DD * DD];   // [n][k] = Wv[k][n] fp16
__device__ float g_wsum[NROWS];

// ---------------------------------------------------------------------------
// helpers
// ---------------------------------------------------------------------------
__device__ __forceinline__ uint32_t smem_u32(const void* p) {
    uint32_t a;
    asm("{ .reg .u64 t; cvta.to.shared.u64 t, %1; cvt.u32.u64 %0, t; }"
        : "=r"(a) : "l"(p));
    return a;
}

__device__ __forceinline__ void cp16(uint32_t dst, const void* src) {
    asm volatile("cp.async.cg.shared.global [%0], [%1], 16;\n"
                 :: "r"(dst), "l"(src));
}

__device__ __forceinline__ uint32_t lds32(uint32_t a) {
    uint32_t v;
    asm volatile("ld.shared.b32 %0, [%1];" : "=r"(v) : "r"(a));
    return v;
}

__device__ __forceinline__ void ldsm_x4(uint32_t* r, uint32_t a) {
    asm volatile("ldmatrix.sync.aligned.m8n8.x4.shared.b16 {%0,%1,%2,%3}, [%4];"
                 : "=r"(r[0]), "=r"(r[1]), "=r"(r[2]), "=r"(r[3]) : "r"(a));
}

__device__ __forceinline__ void mma16816(float* c, const uint32_t* a,
                                         const uint32_t* b) {
    asm volatile(
        "mma.sync.aligned.m16n8k16.row.col.f32.f16.f16.f32 "
        "{%0,%1,%2,%3}, {%4,%5,%6,%7}, {%8,%9}, {%0,%1,%2,%3};"
        : "+f"(c[0]), "+f"(c[1]), "+f"(c[2]), "+f"(c[3])
        : "r"(a[0]), "r"(a[1]), "r"(a[2]), "r"(a[3]), "r"(b[0]), "r"(b[1]));
}

// ---------------------------------------------------------------------------
// Kernel 1: bilinear blend -> fp16 A
// ---------------------------------------------------------------------------
__global__ __launch_bounds__(192) void blend_kernel(
    const float* __restrict__ x,
    const int*   __restrict__ img_ids,
    const float* __restrict__ avgs,
    const float* __restrict__ stds,
    const float* __restrict__ noise)
{
    const int r = blockIdx.x;
    const int b = r / PP;
    const int p = r - b * PP;

    __shared__ int   si[4];
    __shared__ float sw[4];
    __shared__ float swsum;

    if (threadIdx.x == 0) {
        const int id = img_ids[b];
        const size_t abase = (size_t)id * (2 * PP);
        const float ax = avgs[abase + p];
        const float ay = avgs[abase + PP + p];
        const float sx = stds[abase + p];
        const float sy = stds[abase + PP + p];
        const float nx = noise[(size_t)b * 2 * PP + p];
        const float ny = noise[(size_t)b * 2 * PP + PP + p];
        const float kx = (nx - ax) / sx;
        const float ky = (ny - ay) / sy;
        const float x1 = ceilf(kx),  x2 = floorf(kx);
        const float y1 = ceilf(ky),  y2 = floorf(ky);
        const float wx1 = 1.0f - fabsf(x1 - kx);
        const float wx2 = 1.0f - fabsf(x2 - kx);
        const float wy1 = 1.0f - fabsf(y1 - ky);
        const float wy2 = 1.0f - fabsf(y2 - ky);
        const float w[4]   = {wx1 * wy1, wx2 * wy1, wx1 * wy2, wx2 * wy2};
        const float pxv[4] = {x1, x2, x1, x2};
        const float pyv[4] = {y1, y1, y2, y2};
        float tsum = 0.0f;
        #pragma unroll
        for (int j = 0; j < 4; ++j) {
            int t = (int)(14.0f * pyv[j] + pxv[j]);
            t %= SS;
            if (t < 0) t += SS;
            si[j] = t;
            sw[j] = w[j];
            tsum += w[j];
        }
        swsum = tsum;
    }
    __syncthreads();

    const int d4 = threadIdx.x;
    const float4* xb = (const float4*)(x + (size_t)b * SS * DD);
    const float w0 = sw[0], w1 = sw[1], w2 = sw[2], w3 = sw[3];
    const float4 v0 = xb[(size_t)si[0] * (DD / 4) + d4];
    const float4 v1 = xb[(size_t)si[1] * (DD / 4) + d4];
    const float4 v2 = xb[(size_t)si[2] * (DD / 4) + d4];
    const float4 v3 = xb[(size_t)si[3] * (DD / 4) + d4];
    float o[4];
    o[0] = w0 * v0.x + w1 * v1.x + w2 * v2.x + w3 * v3.x;
    o[1] = w0 * v0.y + w1 * v1.y + w2 * v2.y + w3 * v3.y;
    o[2] = w0 * v0.z + w1 * v1.z + w2 * v2.z + w3 * v3.z;
    o[3] = w0 * v0.w + w1 * v1.w + w2 * v2.w + w3 * v3.w;

    ushort4 hv;
    unsigned short* hp = (unsigned short*)&hv;
    #pragma unroll
    for (int j = 0; j < 4; ++j)
        hp[j] = __half_as_ushort(__float2half_rn(o[j]));
    ((ushort4*)g_Ah)[(size_t)r * (DD / 4) + d4] = hv;
    if (threadIdx.x == 0) g_wsum[r] = swsum;
}

// ---------------------------------------------------------------------------
// Kernel 2: transpose Wv -> fp16 B[n][k]
// ---------------------------------------------------------------------------
__global__ __launch_bounds__(256) void wsplit_kernel(const float* __restrict__ W)
{
    __shared__ float t[32][33];
    const int n0 = blockIdx.x * 32, k0 = blockIdx.y * 32;
    const int tx = threadIdx.x & 31, ty = threadIdx.x >> 5;
    #pragma unroll
    for (int r = ty; r < 32; r += 8)
        t[r][tx] = W[(size_t)(k0 + r) * DD + n0 + tx];
    __syncthreads();
    #pragma unroll
    for (int r = ty; r < 32; r += 8)
        g_Bh[(size_t)(n0 + r) * DD + k0 + tx] = __float2half_rn(t[tx][r]);
}

// ---------------------------------------------------------------------------
// Kernel 3: class-token rows -> 1.0
// ---------------------------------------------------------------------------
__global__ __launch_bounds__(192) void cls_kernel(float* __restrict__ out)
{
    const float4 one = make_float4(1.0f, 1.0f, 1.0f, 1.0f);
    ((float4*)(out + (size_t)blockIdx.x * SS * DD))[threadIdx.x] = one;
}

// ---------------------------------------------------------------------------
// Kernel 4: mma.sync fp16 GEMM (single pass).
// CTA 128x128, 8 warps (warp 64x32), Kstage=32, 6-stage cp.async, 96KB smem
// -> 2 CTAs/SM. 64B-pitch rows, XOR chunk swizzle keeps ldmatrix + b32
// fragment loads conflict-free.
// ---------------------------------------------------------------------------
#define ARR_B 8192               // 128 rows * 64B
#define STG_B (2 * ARR_B)        // 16384
#define OFF_A 0
#define OFF_B ARR_B
#define NSTAGE 6
#define KSTEPS 24                // 768 / 32
#define GEMM_SMEM (NSTAGE * STG_B)   // 98304

__device__ __forceinline__ void load_stage(uint32_t sbase, int k0,
                                           int bm, int bn, int tid)
{
    const int row = tid >> 1;          // 0..127
    const int ch0 = (tid & 1) * 2;     // chunks {0,1} or {2,3}
    const int swz = (row >> 1) & 3;

    const __half* pA = g_Ah + (size_t)(bm + row) * DD + k0;
    const __half* pB = g_Bh + (size_t)(bn + row) * DD + k0;
    const uint32_t drow = sbase + (uint32_t)row * 64;

    #pragma unroll
    for (int j = 0; j < 2; ++j) {
        const int ch = ch0 + j;
        const uint32_t d = drow + ((ch ^ swz) << 4);
        const int kk = ch * 8;
        cp16(d + OFF_A, pA + kk);
        cp16(d + OFF_B, pB + kk);
    }
}

__global__ __launch_bounds__(256, 2) void gemm_kernel(
    const float* __restrict__ bv,
    float* __restrict__ out)
{
    extern __shared__ char smem[];
    const uint32_t sb = smem_u32(smem);
    const int tid = threadIdx.x;
    const int lid = tid & 31;
    const int wid = tid >> 5;
    const int bm = blockIdx.y * 128;
    const int bn = blockIdx.x * 128;
    const int wm = (wid & 1) * 64;
    const int wn = (wid >> 1) * 32;

    float acc[4][4][4];
    #pragma unroll
    for (int i = 0; i < 4; ++i)
        #pragma unroll
        for (int j = 0; j < 4; ++j)
            #pragma unroll
            for (int q = 0; q < 4; ++q) acc[i][j][q] = 0.0f;

    #pragma unroll
    for (int s = 0; s < NSTAGE - 1; ++s) {
        load_stage(sb + s * STG_B, s * 32, bm, bn, tid);
        asm volatile("cp.async.commit_group;" ::: "memory");
    }

    // A ldmatrix addressing
    const uint32_t a_row  = (uint32_t)(wm + (lid & 15));
    const uint32_t a_swz  = ((lid & 15) >> 1) & 3;
    const uint32_t a_chb  = (uint32_t)(lid >> 4);     // 0 or 1
    const uint32_t a_base = a_row * 64;
    // B b32 addressing
    const uint32_t b_row  = (uint32_t)(wn + (lid >> 2));
    const uint32_t b_swz  = (lid >> 3) & 3;
    const uint32_t b_base = b_row * 64 + (uint32_t)(lid & 3) * 4;

    #pragma unroll 1
    for (int s = 0; s < KSTEPS; ++s) {
        asm volatile("cp.async.wait_group 4;" ::: "memory");
        __syncthreads();

        if (s + NSTAGE - 1 < KSTEPS)
            load_stage(sb + ((s + NSTAGE - 1) % NSTAGE) * STG_B,
                       (s + NSTAGE - 1) * 32, bm, bn, tid);
        asm volatile("cp.async.commit_group;" ::: "memory");

        const uint32_t st = sb + (s % NSTAGE) * STG_B;
        #pragma unroll
        for (int kb2 = 0; kb2 < 2; ++kb2) {
            uint32_t Ah[4][4], Bh[4][2];
            const uint32_t a_ch = ((kb2 * 2 + a_chb) ^ a_swz) << 4;
            #pragma unroll
            for (int mt = 0; mt < 4; ++mt)
                ldsm_x4(Ah[mt], st + OFF_A + a_base + mt * 1024 + a_ch);
            #pragma unroll
            for (int nt = 0; nt < 4; ++nt) {
                const uint32_t bd = st + OFF_B + b_base + nt * 512;
                Bh[nt][0] = lds32(bd + (((kb2 * 2 + 0) ^ b_swz) << 4));
                Bh[nt][1] = lds32(bd + (((kb2 * 2 + 1) ^ b_swz) << 4));
            }
            #pragma unroll
            for (int mt = 0; mt < 4; ++mt)
                #pragma unroll
                for (int nt = 0; nt < 4; ++nt)
                    mma16816(acc[mt][nt], Ah[mt], Bh[nt]);
        }
    }

    // epilogue: D + wsum[m]*bv[n], scatter row m -> out[b, 1+p, :]
    const int lr2 = lid >> 2;
    const int lc  = (lid & 3) * 2;
    #pragma unroll
    for (int mt = 0; mt < 4; ++mt) {
        #pragma unroll
        for (int half = 0; half < 2; ++half) {
            const int m = bm + wm + mt * 16 + lr2 + half * 8;
            const float ws = g_wsum[m];
            const int b_ = m / PP;
            const int srow = 1 + (m - b_ * PP);
            float* op = out + ((size_t)b_ * SS + srow) * DD + bn + wn;
            #pragma unroll
            for (int nt = 0; nt < 4; ++nt) {
                const float2 bb = *(const float2*)(bv + bn + wn + nt * 8 + lc);
                float2 o;
                o.x = acc[mt][nt][half * 2 + 0] + ws * bb.x;
                o.y = acc[mt][nt][half * 2 + 1] + ws * bb.y;
                *(float2*)(op + nt * 8 + lc) = o;
            }
        }
    }
}

// ---------------------------------------------------------------------------
// Launch
// ---------------------------------------------------------------------------
extern "C" void kernel_launch(void* const* d_in, const int* in_sizes, int n_in,
                              void* d_out, int out_size)
{
    const float* x       = (const float*)d_in[0];
    const int*   img_ids = (const int*)  d_in[1];
    const float* Wv      = (const float*)d_in[7];
    const float* bv      = (const float*)d_in[8];
    const float* avgs    = (const float*)d_in[9];
    const float* stds    = (const float*)d_in[10];
    const float* noise   = (const float*)d_in[11];
    float* out = (float*)d_out;

    cudaFuncSetAttribute(gemm_kernel,
                         cudaFuncAttributeMaxDynamicSharedMemorySize, GEMM_SMEM);

    blend_kernel<<<NROWS, 192>>>(x, img_ids, avgs, stds, noise);
    wsplit_kernel<<<dim3(24, 24), 256>>>(Wv);
    cls_kernel<<<BB, 192>>>(out);
    gemm_kernel<<<dim3(DD / 128, NROWS / 128), 256, GEMM_SMEM>>>(bv, out);
}